// round 8
// baseline (speedup 1.0000x reference)
#include <cuda_runtime.h>
#include <cuda_bf16.h>
#include <mma.h>
#include <cstdint>

using namespace nvcuda;

// Problem constants (fixed by the dataset)
#define MAXN 50000
#define MAXE 400000
#define HD 256          // H * D
#define D_DIM 128
#define NEG_SLOPE 0.2f

// ---------------- scratch (no allocations allowed) ----------------
__device__ float g_xl[(size_t)MAXN * HD];      // source projection  [N,256]
__device__ float g_xr[(size_t)MAXN * HD];      // target projection  [N,256]
__device__ float g_numer[(size_t)MAXN * HD];   // weighted sums (un-normalized)
__device__ float g_denom[(size_t)MAXN * 2];    // sum of exp(score) per node/head

__device__ __forceinline__ void red_add_v4(float* p, float a, float b, float c, float d) {
    asm volatile("red.global.add.v4.f32 [%0], {%1,%2,%3,%4};"
                 :: "l"(p), "f"(a), "f"(b), "f"(c), "f"(d) : "memory");
}

// ---------------- init: zero numer + denom ----------------
__global__ void init_kernel(int n_nodes) {
    int i = blockIdx.x * blockDim.x + threadIdx.x;
    int t4 = n_nodes * 64;                      // float4 count of numer
    if (i < t4) ((float4*)g_numer)[i] = make_float4(0.f, 0.f, 0.f, 0.f);
    if (i < n_nodes * 2) g_denom[i] = 0.f;
}

// ---------------- tf32 tensor-core GEMM (4 warps, 64x64 warp tiles) ----------------
// mode 0: fused projections. A = x [M,128], grid.x = 4 covers 512 output cols:
//         bn<256 -> Wl/bl -> g_xl col (bn&255);  bn>=256 -> Wr/br -> g_xr col (bn&255)
// mode 1: final projection. A = g_numer [M,256] normalized on load
//         (/denom + bias_conv), W = Wa (=Wo), bias = biasa (=bo), C = Cparam [M,128]
#define BM 128
#define BN 128
#define BK 32
#define BKP 40          // padded smem stride

__global__ __launch_bounds__(128, 2) void gemm_tf32(
    const float* __restrict__ Aparam,
    const float* __restrict__ Wa, const float* __restrict__ Wb,
    const float* __restrict__ biasa, const float* __restrict__ biasb,
    const float* __restrict__ bias_conv,
    float* __restrict__ Cparam, int mode, int M, int K)
{
    __shared__ float As[BM][BKP];
    __shared__ float Bs[BN][BKP];

    int tid  = threadIdx.x;
    int wid  = tid >> 5;
    int lane = tid & 31;
    int bm = blockIdx.y * BM;
    int bn = blockIdx.x * BN;

    const float* A;
    const float* W;
    const float* bias;
    float* C;
    int Ncol, cbase;
    if (mode == 0) {
        A = Aparam;
        bool second = bn >= 256;
        int wrow = bn & 255;
        W    = (second ? Wb : Wa) + (size_t)wrow * K;
        bias = (second ? biasb : biasa) + wrow;
        C    = second ? g_xr : g_xl;
        Ncol = HD; cbase = wrow;
    } else {
        A = g_numer;
        W = Wa; bias = biasa;
        C = Cparam; Ncol = D_DIM; cbase = 0;
    }

    // warp tiling: 2x2 warps, each 64x64
    int wm = (wid >> 1) * 64;
    int wn = (wid & 1) * 64;

    // ---- bias -> accumulator init (bias tile overlaid in As region) ----
    float* bias_s = &As[0][0];                  // 16 x 128 row-replicated
    for (int i = tid; i < 16 * BN; i += 128) bias_s[i] = bias[i & 127];
    __syncthreads();

    wmma::fragment<wmma::accumulator, 16, 16, 8, float> acc[4][4];
#pragma unroll
    for (int i = 0; i < 4; i++)
#pragma unroll
        for (int j = 0; j < 4; j++)
            wmma::load_matrix_sync(acc[i][j], bias_s + wn + j * 16, BN, wmma::mem_row_major);
    __syncthreads();

    int lr = tid >> 3;            // 0..15
    int lc = (tid & 7) * 4;       // 0,4,...,28

    for (int k0 = 0; k0 < K; k0 += BK) {
        int head = (k0 >= D_DIM) ? 1 : 0;       // used only in mode 1 (K=256)
        // load A tile 128x32, convert to tf32 once while staging
#pragma unroll
        for (int rr = 0; rr < 8; rr++) {
            int row = rr * 16 + lr;
            int grow = bm + row;
            float4 v = make_float4(0.f, 0.f, 0.f, 0.f);
            if (grow < M) {
                v = *(const float4*)(A + (size_t)grow * K + k0 + lc);
                if (mode == 1) {
                    float inv = 1.0f / (g_denom[(size_t)grow * 2 + head] + 1e-16f);
                    float4 bc = *(const float4*)(bias_conv + k0 + lc);
                    v.x = v.x * inv + bc.x; v.y = v.y * inv + bc.y;
                    v.z = v.z * inv + bc.z; v.w = v.w * inv + bc.w;
                }
            }
            v.x = wmma::__float_to_tf32(v.x); v.y = wmma::__float_to_tf32(v.y);
            v.z = wmma::__float_to_tf32(v.z); v.w = wmma::__float_to_tf32(v.w);
            *(float4*)&As[row][lc] = v;
        }
        // load W tile 128x32 (local rows 0..127 of this block's W slice)
#pragma unroll
        for (int rr = 0; rr < 8; rr++) {
            int row = rr * 16 + lr;
            float4 v = *(const float4*)(W + (size_t)row * K + k0 + lc);
            v.x = wmma::__float_to_tf32(v.x); v.y = wmma::__float_to_tf32(v.y);
            v.z = wmma::__float_to_tf32(v.z); v.w = wmma::__float_to_tf32(v.w);
            *(float4*)&Bs[row][lc] = v;
        }
        __syncthreads();

#pragma unroll
        for (int kk = 0; kk < BK; kk += 8) {
            wmma::fragment<wmma::matrix_a, 16, 16, 8, wmma::precision::tf32, wmma::row_major> af[4];
            wmma::fragment<wmma::matrix_b, 16, 16, 8, wmma::precision::tf32, wmma::col_major> bf[4];
#pragma unroll
            for (int i = 0; i < 4; i++)
                wmma::load_matrix_sync(af[i], &As[wm + i * 16][kk], BKP);
#pragma unroll
            for (int j = 0; j < 4; j++)
                wmma::load_matrix_sync(bf[j], &Bs[wn + j * 16][kk], BKP);
#pragma unroll
            for (int i = 0; i < 4; i++)
#pragma unroll
                for (int j = 0; j < 4; j++)
                    wmma::mma_sync(acc[i][j], af[i], bf[j], acc[i][j]);
        }
        __syncthreads();
    }

    // epilogue
    if (bm + BM <= M) {
#pragma unroll
        for (int i = 0; i < 4; i++)
#pragma unroll
            for (int j = 0; j < 4; j++)
                wmma::store_matrix_sync(C + (size_t)(bm + wm + i * 16) * Ncol + cbase + wn + j * 16,
                                        acc[i][j], Ncol, wmma::mem_row_major);
    } else {
        // remainder block: stage each 16x16 fragment in per-warp smem, guarded writes
        float* sw = ((float*)As) + wid * (16 * 20);
#pragma unroll
        for (int i = 0; i < 4; i++)
#pragma unroll
            for (int j = 0; j < 4; j++) {
                wmma::store_matrix_sync(sw, acc[i][j], 20, wmma::mem_row_major);
                __syncwarp();
                int r  = lane >> 1;
                int c0 = (lane & 1) * 8;
                int grow = bm + wm + i * 16 + r;
                if (grow < M) {
                    float* dst = C + (size_t)grow * Ncol + cbase + wn + j * 16 + c0;
#pragma unroll
                    for (int c = 0; c < 8; c++) dst[c] = sw[r * 20 + c0 + c];
                }
                __syncwarp();
            }
    }
}

// ---------------- edge pass, one head per launch, 2 edges per warp ----------------
// Working set per pass: xl/xr/numer half-slices = 77MB -> L2-resident.
// Two edges per warp double the independent gather chains (latency hiding).
__global__ __launch_bounds__(256) void edge_head_kernel(
    const int* __restrict__ ei, const float* __restrict__ att,
    int E, int n_nodes, int h)
{
    int gw = (blockIdx.x * blockDim.x + threadIdx.x) >> 5;
    int lane = threadIdx.x & 31;
    int ET = E + n_nodes;
    int e0 = gw * 2, e1 = gw * 2 + 1;
    if (e0 >= ET) return;

    int s0, d0;
    if (e0 < E) { s0 = ei[e0]; d0 = ei[(size_t)E + e0]; }
    else        { s0 = d0 = e0 - E; }
    bool v0 = (unsigned)s0 < (unsigned)n_nodes && (unsigned)d0 < (unsigned)n_nodes;

    int s1 = 0, d1 = 0;
    bool v1 = e1 < ET;
    if (v1) {
        if (e1 < E) { s1 = ei[e1]; d1 = ei[(size_t)E + e1]; }
        else        { s1 = d1 = e1 - E; }
        v1 = (unsigned)s1 < (unsigned)n_nodes && (unsigned)d1 < (unsigned)n_nodes;
    }

    const float4* attp = (const float4*)(att + h * D_DIM);
    float4 at = attp[lane];

    float4 a0 = make_float4(0.f,0.f,0.f,0.f), b0 = a0, a1 = a0, b1 = a0;
    if (v0) {
        a0 = ((const float4*)(g_xl + (size_t)s0 * HD + h * D_DIM))[lane];
        b0 = ((const float4*)(g_xr + (size_t)d0 * HD + h * D_DIM))[lane];
    }
    if (v1) {
        a1 = ((const float4*)(g_xl + (size_t)s1 * HD + h * D_DIM))[lane];
        b1 = ((const float4*)(g_xr + (size_t)d1 * HD + h * D_DIM))[lane];
    }

    float ex, ey, ez, ew;
    ex = a0.x + b0.x; ey = a0.y + b0.y; ez = a0.z + b0.z; ew = a0.w + b0.w;
    ex = ex > 0.f ? ex : NEG_SLOPE * ex;
    ey = ey > 0.f ? ey : NEG_SLOPE * ey;
    ez = ez > 0.f ? ez : NEG_SLOPE * ez;
    ew = ew > 0.f ? ew : NEG_SLOPE * ew;
    float dot0 = ex * at.x + ey * at.y + ez * at.z + ew * at.w;

    ex = a1.x + b1.x; ey = a1.y + b1.y; ez = a1.z + b1.z; ew = a1.w + b1.w;
    ex = ex > 0.f ? ex : NEG_SLOPE * ex;
    ey = ey > 0.f ? ey : NEG_SLOPE * ey;
    ez = ez > 0.f ? ez : NEG_SLOPE * ez;
    ew = ew > 0.f ? ew : NEG_SLOPE * ew;
    float dot1 = ex * at.x + ey * at.y + ez * at.z + ew * at.w;

#pragma unroll
    for (int o = 16; o > 0; o >>= 1) {
        dot0 += __shfl_xor_sync(0xffffffffu, dot0, o);
        dot1 += __shfl_xor_sync(0xffffffffu, dot1, o);
    }
    float p0 = __expf(dot0);
    float p1 = __expf(dot1);

    if (lane == 0 && v0) atomicAdd(&g_denom[(size_t)d0 * 2 + h], p0);
    if (lane == 1 && v1) atomicAdd(&g_denom[(size_t)d1 * 2 + h], p1);

    if (v0) {
        float* np = g_numer + (size_t)d0 * HD + h * D_DIM;
        red_add_v4(np + lane * 4, a0.x * p0, a0.y * p0, a0.z * p0, a0.w * p0);
    }
    if (v1) {
        float* np = g_numer + (size_t)d1 * HD + h * D_DIM;
        red_add_v4(np + lane * 4, a1.x * p1, a1.y * p1, a1.z * p1, a1.w * p1);
    }
}

// ---------------- launch ----------------
extern "C" void kernel_launch(void* const* d_in, const int* in_sizes, int n_in,
                              void* d_out, int out_size)
{
    const float* x         = (const float*)d_in[0];
    const int*   ei        = (const int*)d_in[1];     // int32 (JAX x64-disabled)
    const float* Wl        = (const float*)d_in[2];
    const float* bl        = (const float*)d_in[3];
    const float* Wr        = (const float*)d_in[4];
    const float* br        = (const float*)d_in[5];
    const float* att       = (const float*)d_in[6];
    const float* bias_conv = (const float*)d_in[7];
    const float* Wo        = (const float*)d_in[8];
    const float* bo        = (const float*)d_in[9];

    int N = in_sizes[0] / D_DIM;
    int E = in_sizes[1] / 2;
    int ET = E + N;

    // init numer/denom
    {
        int t = N * 64;
        init_kernel<<<(t + 255) / 256, 256>>>(N);
    }
    // fused projections: xl = x@Wl^T+bl, xr = x@Wr^T+br in one launch
    {
        dim3 grid(4, (N + BM - 1) / BM);
        gemm_tf32<<<grid, 128>>>(x, Wl, Wr, bl, br, nullptr, nullptr, 0, N, D_DIM);
    }
    // edge passes: one per head, 2 edges per warp
    {
        int warps = (ET + 1) / 2;
        int blocks = (warps + 7) / 8;
        edge_head_kernel<<<blocks, 256>>>(ei, att, E, N, 0);
        edge_head_kernel<<<blocks, 256>>>(ei, att, E, N, 1);
    }
    // final projection with fused normalize: out = (numer/denom + bias_conv)@Wo^T + bo
    {
        dim3 grid(1, (N + BM - 1) / BM);
        gemm_tf32<<<grid, 128>>>(nullptr, Wo, nullptr, bo, nullptr, bias_conv,
                                 (float*)d_out, 1, N, HD);
    }
}

// round 9
// speedup vs baseline: 1.2544x; 1.2544x over previous
#include <cuda_runtime.h>
#include <cuda_bf16.h>
#include <mma.h>
#include <cstdint>

using namespace nvcuda;

// Problem constants (fixed by the dataset)
#define MAXN 50000
#define MAXE 400000
#define HD 256          // H * D
#define D_DIM 128
#define NEG_SLOPE 0.2f

// ---------------- scratch (no allocations allowed) ----------------
__device__ float g_xl[(size_t)MAXN * HD];      // source projection  [N,256]
__device__ float g_xr[(size_t)MAXN * HD];      // target projection  [N,256]
__device__ float g_numer[(size_t)MAXN * HD];   // weighted sums (un-normalized)
__device__ float g_denom[(size_t)MAXN * 2];    // sum of exp(score) per node/head

__device__ __forceinline__ void red_add_v4(float* p, float a, float b, float c, float d) {
    asm volatile("red.global.add.v4.f32 [%0], {%1,%2,%3,%4};"
                 :: "l"(p), "f"(a), "f"(b), "f"(c), "f"(d) : "memory");
}

// ---------------- init: zero numer + denom ----------------
__global__ void init_kernel(int n_nodes) {
    int i = blockIdx.x * blockDim.x + threadIdx.x;
    int t4 = n_nodes * 64;                      // float4 count of numer
    if (i < t4) ((float4*)g_numer)[i] = make_float4(0.f, 0.f, 0.f, 0.f);
    if (i < n_nodes * 2) g_denom[i] = 0.f;
}

// ---------------- tf32 tensor-core GEMM (8 warps, 64x32 warp tiles — R7 config) ----------------
// mode 0: fused projections. A = x [M,128], grid.x = 4 covers 512 output cols:
//         bn<256 -> Wl/bl -> g_xl col (bn&255);  bn>=256 -> Wr/br -> g_xr col (bn&255)
// mode 1: final projection. A = g_numer [M,256] normalized on load
//         (/denom + bias_conv), W = Wa (=Wo), bias = biasa (=bo), C = Cparam [M,128]
#define BM 128
#define BN 128
#define BK 32
#define BKP 40          // padded smem stride

__global__ __launch_bounds__(256, 2) void gemm_tf32(
    const float* __restrict__ Aparam,
    const float* __restrict__ Wa, const float* __restrict__ Wb,
    const float* __restrict__ biasa, const float* __restrict__ biasb,
    const float* __restrict__ bias_conv,
    float* __restrict__ Cparam, int mode, int M, int K)
{
    __shared__ float As[BM][BKP];
    __shared__ float Bs[BN][BKP];

    int tid  = threadIdx.x;
    int wid  = tid >> 5;
    int lane = tid & 31;
    int bm = blockIdx.y * BM;
    int bn = blockIdx.x * BN;

    const float* A;
    const float* W;
    const float* bias;
    float* C;
    int Ncol, cbase;
    if (mode == 0) {
        A = Aparam;
        bool second = bn >= 256;
        int wrow = bn & 255;
        W    = (second ? Wb : Wa) + (size_t)wrow * K;
        bias = (second ? biasb : biasa) + wrow;
        C    = second ? g_xr : g_xl;
        Ncol = HD; cbase = wrow;
    } else {
        A = g_numer;
        W = Wa; bias = biasa;
        C = Cparam; Ncol = D_DIM; cbase = 0;
    }

    // warp tiling: 2 warps along M (64 rows), 4 along N (32 cols)
    int wm = (wid & 1) * 64;
    int wn = (wid >> 1) * 32;

    // ---- bias -> accumulator init (bias tile overlaid in As region) ----
    float* bias_s = &As[0][0];                  // 16 x 128 row-replicated
    for (int i = tid; i < 16 * BN; i += 256) bias_s[i] = bias[i & 127];
    __syncthreads();

    wmma::fragment<wmma::accumulator, 16, 16, 8, float> acc[4][2];
#pragma unroll
    for (int i = 0; i < 4; i++)
#pragma unroll
        for (int j = 0; j < 2; j++)
            wmma::load_matrix_sync(acc[i][j], bias_s + wn + j * 16, BN, wmma::mem_row_major);
    __syncthreads();

    int lr = tid >> 3;            // 0..31
    int lc = (tid & 7) * 4;       // 0,4,...,28

    for (int k0 = 0; k0 < K; k0 += BK) {
        int head = (k0 >= D_DIM) ? 1 : 0;       // used only in mode 1 (K=256)
        // load A tile 128x32, convert to tf32 once while staging
#pragma unroll
        for (int rr = 0; rr < 4; rr++) {
            int row = rr * 32 + lr;
            int grow = bm + row;
            float4 v = make_float4(0.f, 0.f, 0.f, 0.f);
            if (grow < M) {
                v = *(const float4*)(A + (size_t)grow * K + k0 + lc);
                if (mode == 1) {
                    float inv = 1.0f / (g_denom[(size_t)grow * 2 + head] + 1e-16f);
                    float4 bc = *(const float4*)(bias_conv + k0 + lc);
                    v.x = v.x * inv + bc.x; v.y = v.y * inv + bc.y;
                    v.z = v.z * inv + bc.z; v.w = v.w * inv + bc.w;
                }
            }
            v.x = wmma::__float_to_tf32(v.x); v.y = wmma::__float_to_tf32(v.y);
            v.z = wmma::__float_to_tf32(v.z); v.w = wmma::__float_to_tf32(v.w);
            *(float4*)&As[row][lc] = v;
        }
        // load W tile 128x32 (local rows 0..127 of this block's W slice)
#pragma unroll
        for (int rr = 0; rr < 4; rr++) {
            int row = rr * 32 + lr;
            float4 v = *(const float4*)(W + (size_t)row * K + k0 + lc);
            v.x = wmma::__float_to_tf32(v.x); v.y = wmma::__float_to_tf32(v.y);
            v.z = wmma::__float_to_tf32(v.z); v.w = wmma::__float_to_tf32(v.w);
            *(float4*)&Bs[row][lc] = v;
        }
        __syncthreads();

#pragma unroll
        for (int kk = 0; kk < BK; kk += 8) {
            wmma::fragment<wmma::matrix_a, 16, 16, 8, wmma::precision::tf32, wmma::row_major> af[4];
            wmma::fragment<wmma::matrix_b, 16, 16, 8, wmma::precision::tf32, wmma::col_major> bf[2];
#pragma unroll
            for (int i = 0; i < 4; i++)
                wmma::load_matrix_sync(af[i], &As[wm + i * 16][kk], BKP);
#pragma unroll
            for (int j = 0; j < 2; j++)
                wmma::load_matrix_sync(bf[j], &Bs[wn + j * 16][kk], BKP);
#pragma unroll
            for (int i = 0; i < 4; i++)
#pragma unroll
                for (int j = 0; j < 2; j++)
                    wmma::mma_sync(acc[i][j], af[i], bf[j], acc[i][j]);
        }
        __syncthreads();
    }

    // epilogue
    if (bm + BM <= M) {
#pragma unroll
        for (int i = 0; i < 4; i++)
#pragma unroll
            for (int j = 0; j < 2; j++)
                wmma::store_matrix_sync(C + (size_t)(bm + wm + i * 16) * Ncol + cbase + wn + j * 16,
                                        acc[i][j], Ncol, wmma::mem_row_major);
    } else {
        // remainder block: stage each 16x16 fragment in per-warp smem, guarded writes
        float* sw = ((float*)As) + wid * (16 * 20);
#pragma unroll
        for (int i = 0; i < 4; i++)
#pragma unroll
            for (int j = 0; j < 2; j++) {
                wmma::store_matrix_sync(sw, acc[i][j], 20, wmma::mem_row_major);
                __syncwarp();
                int r  = lane >> 1;
                int c0 = (lane & 1) * 8;
                int grow = bm + wm + i * 16 + r;
                if (grow < M) {
                    float* dst = C + (size_t)grow * Ncol + cbase + wn + j * 16 + c0;
#pragma unroll
                    for (int c = 0; c < 8; c++) dst[c] = sw[r * 20 + c0 + c];
                }
                __syncwarp();
            }
    }
}

// ---------------- edge pass, one head per launch, 2 edges per warp (R8 config) ----------------
// Working set per pass: xl/xr/numer half-slices = 77MB -> L2-resident.
// Two edges per warp double the independent gather chains (latency hiding).
__global__ __launch_bounds__(256) void edge_head_kernel(
    const int* __restrict__ ei, const float* __restrict__ att,
    int E, int n_nodes, int h)
{
    int gw = (blockIdx.x * blockDim.x + threadIdx.x) >> 5;
    int lane = threadIdx.x & 31;
    int ET = E + n_nodes;
    int e0 = gw * 2, e1 = gw * 2 + 1;
    if (e0 >= ET) return;

    int s0, d0;
    if (e0 < E) { s0 = ei[e0]; d0 = ei[(size_t)E + e0]; }
    else        { s0 = d0 = e0 - E; }
    bool v0 = (unsigned)s0 < (unsigned)n_nodes && (unsigned)d0 < (unsigned)n_nodes;

    int s1 = 0, d1 = 0;
    bool v1 = e1 < ET;
    if (v1) {
        if (e1 < E) { s1 = ei[e1]; d1 = ei[(size_t)E + e1]; }
        else        { s1 = d1 = e1 - E; }
        v1 = (unsigned)s1 < (unsigned)n_nodes && (unsigned)d1 < (unsigned)n_nodes;
    }

    const float4* attp = (const float4*)(att + h * D_DIM);
    float4 at = attp[lane];

    float4 a0 = make_float4(0.f,0.f,0.f,0.f), b0 = a0, a1 = a0, b1 = a0;
    if (v0) {
        a0 = ((const float4*)(g_xl + (size_t)s0 * HD + h * D_DIM))[lane];
        b0 = ((const float4*)(g_xr + (size_t)d0 * HD + h * D_DIM))[lane];
    }
    if (v1) {
        a1 = ((const float4*)(g_xl + (size_t)s1 * HD + h * D_DIM))[lane];
        b1 = ((const float4*)(g_xr + (size_t)d1 * HD + h * D_DIM))[lane];
    }

    float ex, ey, ez, ew;
    ex = a0.x + b0.x; ey = a0.y + b0.y; ez = a0.z + b0.z; ew = a0.w + b0.w;
    ex = ex > 0.f ? ex : NEG_SLOPE * ex;
    ey = ey > 0.f ? ey : NEG_SLOPE * ey;
    ez = ez > 0.f ? ez : NEG_SLOPE * ez;
    ew = ew > 0.f ? ew : NEG_SLOPE * ew;
    float dot0 = ex * at.x + ey * at.y + ez * at.z + ew * at.w;

    ex = a1.x + b1.x; ey = a1.y + b1.y; ez = a1.z + b1.z; ew = a1.w + b1.w;
    ex = ex > 0.f ? ex : NEG_SLOPE * ex;
    ey = ey > 0.f ? ey : NEG_SLOPE * ey;
    ez = ez > 0.f ? ez : NEG_SLOPE * ez;
    ew = ew > 0.f ? ew : NEG_SLOPE * ew;
    float dot1 = ex * at.x + ey * at.y + ez * at.z + ew * at.w;

#pragma unroll
    for (int o = 16; o > 0; o >>= 1) {
        dot0 += __shfl_xor_sync(0xffffffffu, dot0, o);
        dot1 += __shfl_xor_sync(0xffffffffu, dot1, o);
    }
    float p0 = __expf(dot0);
    float p1 = __expf(dot1);

    if (lane == 0 && v0) atomicAdd(&g_denom[(size_t)d0 * 2 + h], p0);
    if (lane == 1 && v1) atomicAdd(&g_denom[(size_t)d1 * 2 + h], p1);

    if (v0) {
        float* np = g_numer + (size_t)d0 * HD + h * D_DIM;
        red_add_v4(np + lane * 4, a0.x * p0, a0.y * p0, a0.z * p0, a0.w * p0);
    }
    if (v1) {
        float* np = g_numer + (size_t)d1 * HD + h * D_DIM;
        red_add_v4(np + lane * 4, a1.x * p1, a1.y * p1, a1.z * p1, a1.w * p1);
    }
}

// ---------------- launch ----------------
extern "C" void kernel_launch(void* const* d_in, const int* in_sizes, int n_in,
                              void* d_out, int out_size)
{
    const float* x         = (const float*)d_in[0];
    const int*   ei        = (const int*)d_in[1];     // int32 (JAX x64-disabled)
    const float* Wl        = (const float*)d_in[2];
    const float* bl        = (const float*)d_in[3];
    const float* Wr        = (const float*)d_in[4];
    const float* br        = (const float*)d_in[5];
    const float* att       = (const float*)d_in[6];
    const float* bias_conv = (const float*)d_in[7];
    const float* Wo        = (const float*)d_in[8];
    const float* bo        = (const float*)d_in[9];

    int N = in_sizes[0] / D_DIM;
    int E = in_sizes[1] / 2;
    int ET = E + N;

    // init numer/denom
    {
        int t = N * 64;
        init_kernel<<<(t + 255) / 256, 256>>>(N);
    }
    // fused projections: xl = x@Wl^T+bl, xr = x@Wr^T+br in one launch
    {
        dim3 grid(4, (N + BM - 1) / BM);
        gemm_tf32<<<grid, 256>>>(x, Wl, Wr, bl, br, nullptr, nullptr, 0, N, D_DIM);
    }
    // edge passes: one per head, 2 edges per warp
    {
        int warps = (ET + 1) / 2;
        int blocks = (warps + 7) / 8;
        edge_head_kernel<<<blocks, 256>>>(ei, att, E, N, 0);
        edge_head_kernel<<<blocks, 256>>>(ei, att, E, N, 1);
    }
    // final projection with fused normalize: out = (numer/denom + bias_conv)@Wo^T + bo
    {
        dim3 grid(1, (N + BM - 1) / BM);
        gemm_tf32<<<grid, 256>>>(nullptr, Wo, nullptr, bo, nullptr, bias_conv,
                                 (float*)d_out, 1, N, HD);
    }
}